// round 16
// baseline (speedup 1.0000x reference)
#include <cuda_runtime.h>
#include <cuda_fp16.h>
#include <cstdint>

#define BATCH 4
#define NPTS  4096
#define KNB   20
#define EPSV  1e-5f
#define SLOPE 0.2f
#define BCAP 128

// knn smem layout (bytes)
#define KS_LM   0          // 16*512 floats = 32768
#define KS_BUF  32768      // 16*128 u64    = 16384
#define KS_QC   49152      // 16*3 floats (+pad) = 256
#define KS_TSH  49408      // 16 floats + pad    = 64
#define KS_CNT  49472      // 16 u32             = 64
#define KS_TOT  49536

// main kernel smem layout (float offsets)
#define OF_WPS 0          // 96 rows * 132 u32 = 12672  (f16x2 B tiles)
#define OF_Z   12672      // 320 * 66  (z epilogue buffer)
#define OF_FT  33792      // 320 * 9
#define OF_X1  36672      // 16 * 64
#define OF_W0  37696      // 384
#define OF_B0  38080      // 64
#define OF_B1  38144      // 64
#define OF_WO  38208      // 192
#define SM_FLOATS 38400   // 153600 bytes

__device__ unsigned g_wb[96 * 128];   // f16x2 B, K-permuted (see prep)
__device__ float    g_w0f[384];
__device__ int      g_idx[BATCH * NPTS * KNB];

__device__ __forceinline__ float lrelu(float v) { return fmaxf(v, SLOPE * v); }

__device__ __forceinline__ unsigned fkey(float d) {
    unsigned b = __float_as_uint(d);
    return b ^ ((unsigned)((int)b >> 31) | 0x80000000u);
}
__device__ __forceinline__ uint32_t packh2(float lo, float hi) {
    uint32_t r;
    asm("cvt.rn.f16x2.f32 %0, %1, %2;" : "=r"(r) : "f"(hi), "f"(lo));
    return r;
}

#define MMA_F16(d, a0, a1, a2, a3, b0, b1) \
    asm volatile("mma.sync.aligned.m16n8k16.row.col.f32.f16.f16.f32 " \
        "{%0,%1,%2,%3}, {%4,%5,%6,%7}, {%8,%9}, {%0,%1,%2,%3};" \
        : "+f"((d)[0]), "+f"((d)[1]), "+f"((d)[2]), "+f"((d)[3]) \
        : "r"(a0), "r"(a1), "r"(a2), "r"(a3), "r"(b0), "r"(b1))

// ---------------------------------------------------------------------------
// KNN: register-tiled, 4 blocks/SM. Grid (NPTS/16, BATCH), 512 thr (16 warps).
// Warp w holds points [w*256, w*256+256) in regs (loaded once).
// Pass 1: per query, per-(warp,lane) min over 8 disjoint points -> lm[q][512].
// Threshold (warp q): lane l aggregates its 16 entries lm[q][l+32u] -> min
// over the 128 points ≡ l (mod 32). 32 disjoint 128-pt parts; T = 20th
// smallest of the 32 lane-mins (with multiplicity) => >=20 distinct points
// have d <= T => global 20th <= T: the filter d <= T is exact. nb ~ 31.
// Pass 2: same registers, rare atomic append of (fkey(d)<<32|idx).
// Phase 3: per-warp exact top-20 via 20 warp-min rounds (ties -> lowest idx).
// Output order irrelevant downstream (max over k).
// ---------------------------------------------------------------------------
__global__ void __launch_bounds__(512, 4) knn_prep_kernel(
    const float* __restrict__ x,
    const float* __restrict__ w0, const float* __restrict__ g0,
    const float* __restrict__ w1, const float* __restrict__ g1)
{
    extern __shared__ char dsm[];
    float*              lm  = reinterpret_cast<float*>(dsm + KS_LM);
    unsigned long long* buf = reinterpret_cast<unsigned long long*>(dsm + KS_BUF);
    float*              qc  = reinterpret_cast<float*>(dsm + KS_QC);
    float*              Tsh = reinterpret_cast<float*>(dsm + KS_TSH);
    unsigned*           cnt = reinterpret_cast<unsigned*>(dsm + KS_CNT);

    const int tid = threadIdx.x, lane = tid & 31, w = tid >> 5;
    const int b = blockIdx.y, q0 = blockIdx.x * 16;
    const float* xb = x + b * 3 * NPTS;
    const float INF = __int_as_float(0x7f800000);

    {   // prep distributed over 1024 blocks (f16x2 B, K-permuted)
        const int gt = (blockIdx.y * gridDim.x + blockIdx.x) * 512 + tid;
        const float inv = rsqrtf(1.f + EPSV);
        if (gt < 384) g_w0f[gt] = w0[gt] * g0[gt / 6] * inv;
        if (gt < 96 * 128) {
            int R = gt >> 7, pos = gt & 127;
            int k16 = R >> 2, s = R & 3;
            int qq = pos >> 4, h = (pos >> 3) & 1, nt = pos & 7;
            int n  = qq + 8 * nt;
            float sc = g1[n] * inv;
            int p0 = 4 * k16 + 2 * h, p1 = p0 + 1;
            int m0 = 4 * (p0 & 15) + s, c0 = p0 >> 4;
            int m1 = 4 * (p1 & 15) + s, c1 = p1 >> 4;
            __half h0 = __float2half_rn(w1[(n * 6 + c0) * 64 + m0] * sc);
            __half h1 = __float2half_rn(w1[(n * 6 + c1) * 64 + m1] * sc);
            g_wb[gt] = (unsigned)__half_as_ushort(h0)
                     | ((unsigned)__half_as_ushort(h1) << 16);
        }
    }

    if (tid < 16) {
        qc[tid * 3 + 0] = xb[q0 + tid];
        qc[tid * 3 + 1] = xb[NPTS + q0 + tid];
        qc[tid * 3 + 2] = xb[2 * NPTS + q0 + tid];
        cnt[tid] = 0;
    }
    __syncthreads();

    // ---- load this warp's 256 points into registers (once) ----
    float4 P[8];
#pragma unroll
    for (int t = 0; t < 8; t++) {
        int j = w * 256 + t * 32 + lane;
        float px = xb[j], py = xb[NPTS + j], pz = xb[2 * NPTS + j];
        P[t] = make_float4(px, py, pz, fmaf(px, px, fmaf(py, py, pz * pz)));
    }

    // ---- pass 1: per-query lane mins ----
#pragma unroll 1
    for (int q = 0; q < 16; q++) {
        float qx = qc[q * 3], qy = qc[q * 3 + 1], qz = qc[q * 3 + 2];
        float mnv = INF;
#pragma unroll
        for (int t = 0; t < 8; t++) {
            float d = fmaf(-2.f, fmaf(qx, P[t].x, fmaf(qy, P[t].y, qz * P[t].z)),
                           P[t].w);
            mnv = fminf(mnv, d);
        }
        lm[q * 512 + w * 32 + lane] = mnv;
    }
    __syncthreads();

    // ---- threshold: warp w handles query w (scalar lane-aggregation) ----
    {
        float val = INF;
#pragma unroll
        for (int u = 0; u < 16; u++)
            val = fminf(val, lm[w * 512 + lane + u * 32]);
        float T = INF;
        for (int r = 0; r < KNB; r++) {
            float wmin = val;
#pragma unroll
            for (int d = 16; d; d >>= 1)
                wmin = fminf(wmin, __shfl_xor_sync(0xffffffffu, wmin, d));
            unsigned msk = __ballot_sync(0xffffffffu, val == wmin);
            if (lane == (__ffs(msk) - 1)) val = INF;
            T = wmin;
        }
        if (lane == 0) Tsh[w] = T;
    }
    __syncthreads();

    // ---- pass 2: compact passers from registers ----
#pragma unroll 1
    for (int q = 0; q < 16; q++) {
        float T = Tsh[q];
        float qx = qc[q * 3], qy = qc[q * 3 + 1], qz = qc[q * 3 + 2];
#pragma unroll
        for (int t = 0; t < 8; t++) {
            float d = fmaf(-2.f, fmaf(qx, P[t].x, fmaf(qy, P[t].y, qz * P[t].z)),
                           P[t].w);
            if (d <= T) {
                unsigned pos = atomicAdd(&cnt[q], 1u);
                if (pos < BCAP) {
                    int j = w * 256 + t * 32 + lane;
                    buf[q * BCAP + pos] =
                        ((unsigned long long)fkey(d) << 32) | (unsigned)j;
                }
            }
        }
    }
    __syncthreads();

    // ---- phase 3: warp w -> exact top-20 of query w ----
    {
        const unsigned nb = cnt[w];
        int* obase = g_idx + (b * NPTS + q0 + w) * KNB;
        if (nb <= BCAP) {
            unsigned long long v[BCAP / 32];
#pragma unroll
            for (int u = 0; u < BCAP / 32; u++) {
                int t = lane + u * 32;
                v[u] = (t < (int)nb) ? buf[w * BCAP + t] : 0xffffffffffffffffull;
            }
            for (int r = 0; r < KNB; r++) {
                unsigned long long lmin = v[0]; int lpos = 0;
#pragma unroll
                for (int u = 1; u < BCAP / 32; u++)
                    if (v[u] < lmin) { lmin = v[u]; lpos = u; }
                unsigned long long wmin = lmin;
#pragma unroll
                for (int d = 16; d; d >>= 1) {
                    unsigned long long o = __shfl_xor_sync(0xffffffffu, wmin, d);
                    wmin = (o < wmin) ? o : wmin;
                }
                if (lmin == wmin) {
#pragma unroll
                    for (int u = 0; u < BCAP / 32; u++)
                        if (u == lpos) v[u] = 0xffffffffffffffffull;
                }
                if (lane == 0) obase[r] = (int)(unsigned)(wmin & 0xffffffffull);
            }
        } else {
            // pathological fallback: exact repeated warp-min over all points
            float qx = qc[w * 3], qy = qc[w * 3 + 1], qz = qc[w * 3 + 2];
            unsigned long long last = 0;
            for (int r = 0; r < KNB; r++) {
                unsigned long long best = 0xffffffffffffffffull;
                for (int t = 0; t < NPTS / 32; t++) {
                    int j = t * 32 + lane;
                    float px = xb[j], py = xb[NPTS + j], pz = xb[2 * NPTS + j];
                    float pp = fmaf(px, px, fmaf(py, py, pz * pz));
                    float d = fmaf(-2.f, fmaf(qx, px, fmaf(qy, py, qz * pz)), pp);
                    unsigned long long kk =
                        ((unsigned long long)fkey(d) << 32) | (unsigned)j;
                    if (kk > last && kk < best) best = kk;
                }
#pragma unroll
                for (int d = 16; d; d >>= 1) {
                    unsigned long long o = __shfl_xor_sync(0xffffffffu, best, d);
                    best = (o < best) ? o : best;
                }
                if (lane == 0) obase[r] = (int)(unsigned)(best & 0xffffffffull);
                last = best;
            }
        }
    }
}

// ---------------------------------------------------------------------------
// Main: f16 mma.sync m16n8k16 GEMM with shfl-free A-operand build (round 14).
// ---------------------------------------------------------------------------
__global__ void __launch_bounds__(640, 1) main_mma(
    const float* __restrict__ x,     const float* __restrict__ b0,
    const float* __restrict__ b1,    const float* __restrict__ w_out,
    const float* __restrict__ g_out, const float* __restrict__ b_out,
    float* __restrict__ out)
{
    extern __shared__ float sm[];
    unsigned* wps = reinterpret_cast<unsigned*>(sm + OF_WPS);  // stride 132 u32
    float* zs  = sm + OF_Z;
    float* fts = sm + OF_FT;
    float* x1s = sm + OF_X1;
    float* w0f = sm + OF_W0;
    float* b0s = sm + OF_B0;
    float* b1s = sm + OF_B1;
    float* wos = sm + OF_WO;

    const int tid = threadIdx.x, lane = tid & 31, wid = tid >> 5;
    const int b = blockIdx.y, p0 = blockIdx.x * 16;
    const float* xb = x + b * 3 * NPTS;

    if (tid < 320) {
        int n = p0 + tid / 20;
        int jn = g_idx[(b * NPTS + n) * KNB + tid % 20];
        float xi0 = xb[n],  xi1 = xb[NPTS + n],  xi2 = xb[2 * NPTS + n];
        float xj0 = xb[jn], xj1 = xb[NPTS + jn], xj2 = xb[2 * NPTS + jn];
        float* fr = fts + tid * 9;
        fr[0] = xj0 - xi0; fr[1] = xj1 - xi1; fr[2] = xj2 - xi2;
        fr[3] = xi0; fr[4] = xi1; fr[5] = xi2;
    }
    for (int g4 = tid; g4 < 3072; g4 += 640) {
        uint4 v = reinterpret_cast<const uint4*>(g_wb)[g4];
        int row = g4 >> 5, pos4 = g4 & 31;
        *reinterpret_cast<uint4*>(wps + row * 132 + pos4 * 4) = v;
    }
    if (tid < 384) w0f[tid] = g_w0f[tid];
    if (tid < 64) { b0s[tid] = b0[tid]; b1s[tid] = b1[tid]; }
    if (tid < 192) wos[tid] = w_out[tid];
    __syncthreads();

    const int s = lane & 3, q = lane >> 2;
    const int rA = wid * 16 + q;

    float yr0[16], yr1[16];
    {
        const float* fA = fts + rA * 9;
        const float* fB = fts + (rA + 8) * 9;
        float a0 = fA[0], a1 = fA[1], a2 = fA[2], a3 = fA[3], a4 = fA[4], a5 = fA[5];
        float c0 = fB[0], c1 = fB[1], c2 = fB[2], c3 = fB[3], c4 = fB[4], c5 = fB[5];
#pragma unroll
        for (int k = 0; k < 16; k++) {
            int m = 4 * k + s;
            const float* wr = w0f + m * 6;
            float bb = b0s[m];
            float u = bb, v = bb;
            u = fmaf(wr[0], a0, u); v = fmaf(wr[0], c0, v);
            u = fmaf(wr[1], a1, u); v = fmaf(wr[1], c1, v);
            u = fmaf(wr[2], a2, u); v = fmaf(wr[2], c2, v);
            u = fmaf(wr[3], a3, u); v = fmaf(wr[3], c3, v);
            u = fmaf(wr[4], a4, u); v = fmaf(wr[4], c4, v);
            u = fmaf(wr[5], a5, u); v = fmaf(wr[5], c5, v);
            yr0[k] = lrelu(u);
            yr1[k] = lrelu(v);
        }
    }

    float ftA[6], ftB[6];
#pragma unroll
    for (int i = 0; i < 6; i++) {
        ftA[i] = fts[rA * 9 + i];
        ftB[i] = fts[(rA + 8) * 9 + i];
    }

    float dA[8][4];
#pragma unroll
    for (int nt = 0; nt < 8; nt++)
#pragma unroll
        for (int u = 0; u < 4; u++) dA[nt][u] = 0.f;

    const unsigned* wbase = wps + s * 132 + q * 16;

#pragma unroll
    for (int k16 = 0; k16 < 24; k16++) {
        const int c  = k16 >> 2;
        const int kb = 4 * (k16 & 3);
        const float fA = ftA[c], fB = ftB[c];

        uint32_t a0 = packh2(yr0[kb] * fA,     yr0[kb + 1] * fA);
        uint32_t a1 = packh2(yr1[kb] * fB,     yr1[kb + 1] * fB);
        uint32_t a2 = packh2(yr0[kb + 2] * fA, yr0[kb + 3] * fA);
        uint32_t a3 = packh2(yr1[kb + 2] * fB, yr1[kb + 3] * fB);

        const unsigned* wrow = wbase + k16 * 4 * 132;
        uint4 B0a = *reinterpret_cast<const uint4*>(wrow);
        uint4 B0b = *reinterpret_cast<const uint4*>(wrow + 4);
        uint4 B1a = *reinterpret_cast<const uint4*>(wrow + 8);
        uint4 B1b = *reinterpret_cast<const uint4*>(wrow + 12);

        MMA_F16(dA[0], a0, a1, a2, a3, B0a.x, B1a.x);
        MMA_F16(dA[1], a0, a1, a2, a3, B0a.y, B1a.y);
        MMA_F16(dA[2], a0, a1, a2, a3, B0a.z, B1a.z);
        MMA_F16(dA[3], a0, a1, a2, a3, B0a.w, B1a.w);
        MMA_F16(dA[4], a0, a1, a2, a3, B0b.x, B1b.x);
        MMA_F16(dA[5], a0, a1, a2, a3, B0b.y, B1b.y);
        MMA_F16(dA[6], a0, a1, a2, a3, B0b.z, B1b.z);
        MMA_F16(dA[7], a0, a1, a2, a3, B0b.w, B1b.w);
    }

    __syncwarp();
#pragma unroll
    for (int nt = 0; nt < 8; nt++) {
        int c = nt * 8 + s * 2;
        float bc0 = b1s[c], bc1 = b1s[c + 1];
        *reinterpret_cast<float2*>(zs + rA * 66 + c) =
            make_float2(lrelu(dA[nt][0] + bc0), lrelu(dA[nt][1] + bc1));
        *reinterpret_cast<float2*>(zs + (rA + 8) * 66 + c) =
            make_float2(lrelu(dA[nt][2] + bc0), lrelu(dA[nt][3] + bc1));
    }
    __syncthreads();

    for (int it = tid; it < 16 * 64; it += 640) {
        int p = it >> 6, col = it & 63;
        const float* zr = zs + (p * 20) * 66 + col;
        float m = -3.4e38f;
#pragma unroll
        for (int kk = 0; kk < 20; kk++) m = fmaxf(m, zr[kk * 66]);
        x1s[it] = m;
    }
    __syncthreads();

    if (tid < 48) {
        int oo = tid >> 4, pt = tid & 15;
        const float* wr = wos + oo * 64;
        const float* xr = x1s + pt * 64;
        float sum = 0.f;
#pragma unroll
        for (int o = 0; o < 64; o++) sum = fmaf(wr[o], xr[o], sum);
        float v = sum * (g_out[oo] * rsqrtf(1.f + EPSV)) + b_out[oo];
        out[(b * 3 + oo) * NPTS + p0 + pt] = lrelu(v);
    }
}

// ---------------------------------------------------------------------------
extern "C" void kernel_launch(void* const* d_in, const int* in_sizes, int n_in,
                              void* d_out, int out_size) {
    const float* x     = (const float*)d_in[0];
    const float* w0    = (const float*)d_in[1];
    const float* g0    = (const float*)d_in[2];
    const float* b0    = (const float*)d_in[3];
    const float* w1    = (const float*)d_in[4];
    const float* g1    = (const float*)d_in[5];
    const float* b1    = (const float*)d_in[6];
    const float* w_out = (const float*)d_in[7];
    const float* g_out = (const float*)d_in[8];
    const float* b_out = (const float*)d_in[9];
    float* out = (float*)d_out;

    const int main_smem = SM_FLOATS * 4;                     // 153600

    cudaFuncSetAttribute(knn_prep_kernel, cudaFuncAttributeMaxDynamicSharedMemorySize,
                         KS_TOT);
    cudaFuncSetAttribute(main_mma, cudaFuncAttributeMaxDynamicSharedMemorySize,
                         main_smem);

    knn_prep_kernel<<<dim3(NPTS / 16, BATCH), 512, KS_TOT>>>(x, w0, g0, w1, g1);
    main_mma<<<dim3(NPTS / 16, BATCH), 640, main_smem>>>(x, b0, b1, w_out,
                                                         g_out, b_out, out);
}

// round 17
// speedup vs baseline: 1.7005x; 1.7005x over previous
#include <cuda_runtime.h>
#include <cuda_fp16.h>
#include <cstdint>

#define BATCH 4
#define NPTS  4096
#define KNB   20
#define EPSV  1e-5f
#define SLOPE 0.2f
#define BCAP 128

// knn smem layout (bytes)
#define KS_LM   0          // 16*512 floats = 32768
#define KS_BUF  32768      // 16*128 u64    = 16384
#define KS_QC   49152      // 16*3 floats (+pad) = 256
#define KS_TSH  49408      // 16 floats + pad    = 64
#define KS_CNT  49472      // 16 u32             = 64
#define KS_TOT  49536

// main kernel smem layout (float offsets)
#define OF_WPS 0          // 96 rows * 132 u32 = 12672  (f16x2 B tiles)
#define OF_Z   12672      // 320 * 66  (z epilogue buffer)
#define OF_FT  33792      // 320 * 9
#define OF_X1  36672      // 16 * 64
#define OF_W0  37696      // 384
#define OF_B0  38080      // 64
#define OF_B1  38144      // 64
#define OF_WO  38208      // 192
#define SM_FLOATS 38400   // 153600 bytes

__device__ unsigned g_wb[96 * 128];   // f16x2 B, K-permuted (see prep)
__device__ float    g_w0f[384];
__device__ int      g_idx[BATCH * NPTS * KNB];

__device__ __forceinline__ float lrelu(float v) { return fmaxf(v, SLOPE * v); }

__device__ __forceinline__ unsigned fkey(float d) {
    unsigned b = __float_as_uint(d);
    return b ^ ((unsigned)((int)b >> 31) | 0x80000000u);
}
__device__ __forceinline__ uint32_t packh2(float lo, float hi) {
    uint32_t r;
    asm("cvt.rn.f16x2.f32 %0, %1, %2;" : "=r"(r) : "f"(hi), "f"(lo));
    return r;
}

#define MMA_F16(d, a0, a1, a2, a3, b0, b1) \
    asm volatile("mma.sync.aligned.m16n8k16.row.col.f32.f16.f16.f32 " \
        "{%0,%1,%2,%3}, {%4,%5,%6,%7}, {%8,%9}, {%0,%1,%2,%3};" \
        : "+f"((d)[0]), "+f"((d)[1]), "+f"((d)[2]), "+f"((d)[3]) \
        : "r"(a0), "r"(a1), "r"(a2), "r"(a3), "r"(b0), "r"(b1))

// ---------------------------------------------------------------------------
// KNN: register-tiled, 2 blocks/SM (occ-4 regression reverted: the 32-reg cap
// spilled the point tile). Rank-based selections (no serial shfl chains).
// Grid (NPTS/16, BATCH), 512 thr (16 warps). Warp w holds points
// [w*256, w*256+256) in regs (loaded once).
// Pass 1: per query, per-(warp,lane) min over 8 disjoint points -> lm[q][512].
// Threshold (warp q): lane l mins its 16 entries (the 128 points ≡ l mod 32 —
// 32 disjoint 128-pt parts); T = rank-19 element of the 32 lane-mins
// (32 indep shfl broadcasts, tie -> lane). >=20 distinct points have d <= T
// => global 20th <= T => filter d <= T is exact.
// Pass 2: same registers, rare atomic append of (fkey(d)<<32|idx).
// Phase 3: rank of each candidate among all nb (distinct keys => bijective);
// rank < 20 writes obase[rank] — exactly the top-20, ties -> lowest idx
// (matches top_k). Output order irrelevant downstream (max over k).
// ---------------------------------------------------------------------------
__global__ void __launch_bounds__(512, 2) knn_prep_kernel(
    const float* __restrict__ x,
    const float* __restrict__ w0, const float* __restrict__ g0,
    const float* __restrict__ w1, const float* __restrict__ g1)
{
    extern __shared__ char dsm[];
    float*              lm  = reinterpret_cast<float*>(dsm + KS_LM);
    unsigned long long* buf = reinterpret_cast<unsigned long long*>(dsm + KS_BUF);
    float*              qc  = reinterpret_cast<float*>(dsm + KS_QC);
    float*              Tsh = reinterpret_cast<float*>(dsm + KS_TSH);
    unsigned*           cnt = reinterpret_cast<unsigned*>(dsm + KS_CNT);

    const int tid = threadIdx.x, lane = tid & 31, w = tid >> 5;
    const int b = blockIdx.y, q0 = blockIdx.x * 16;
    const float* xb = x + b * 3 * NPTS;
    const float INF = __int_as_float(0x7f800000);

    {   // prep distributed over 1024 blocks (f16x2 B, K-permuted)
        const int gt = (blockIdx.y * gridDim.x + blockIdx.x) * 512 + tid;
        const float inv = rsqrtf(1.f + EPSV);
        if (gt < 384) g_w0f[gt] = w0[gt] * g0[gt / 6] * inv;
        if (gt < 96 * 128) {
            int R = gt >> 7, pos = gt & 127;
            int k16 = R >> 2, s = R & 3;
            int qq = pos >> 4, h = (pos >> 3) & 1, nt = pos & 7;
            int n  = qq + 8 * nt;
            float sc = g1[n] * inv;
            int p0 = 4 * k16 + 2 * h, p1 = p0 + 1;
            int m0 = 4 * (p0 & 15) + s, c0 = p0 >> 4;
            int m1 = 4 * (p1 & 15) + s, c1 = p1 >> 4;
            __half h0 = __float2half_rn(w1[(n * 6 + c0) * 64 + m0] * sc);
            __half h1 = __float2half_rn(w1[(n * 6 + c1) * 64 + m1] * sc);
            g_wb[gt] = (unsigned)__half_as_ushort(h0)
                     | ((unsigned)__half_as_ushort(h1) << 16);
        }
    }

    if (tid < 16) {
        qc[tid * 3 + 0] = xb[q0 + tid];
        qc[tid * 3 + 1] = xb[NPTS + q0 + tid];
        qc[tid * 3 + 2] = xb[2 * NPTS + q0 + tid];
        cnt[tid] = 0;
    }
    __syncthreads();

    // ---- load this warp's 256 points into registers (once) ----
    float4 P[8];
#pragma unroll
    for (int t = 0; t < 8; t++) {
        int j = w * 256 + t * 32 + lane;
        float px = xb[j], py = xb[NPTS + j], pz = xb[2 * NPTS + j];
        P[t] = make_float4(px, py, pz, fmaf(px, px, fmaf(py, py, pz * pz)));
    }

    // ---- pass 1: per-query lane mins ----
#pragma unroll 1
    for (int q = 0; q < 16; q++) {
        float qx = qc[q * 3], qy = qc[q * 3 + 1], qz = qc[q * 3 + 2];
        float mnv = INF;
#pragma unroll
        for (int t = 0; t < 8; t++) {
            float d = fmaf(-2.f, fmaf(qx, P[t].x, fmaf(qy, P[t].y, qz * P[t].z)),
                           P[t].w);
            mnv = fminf(mnv, d);
        }
        lm[q * 512 + w * 32 + lane] = mnv;
    }
    __syncthreads();

    // ---- threshold (warp w, query w): rank-select the 20th lane-min ----
    {
        float val = INF;
#pragma unroll
        for (int u = 0; u < 16; u++)
            val = fminf(val, lm[w * 512 + lane + u * 32]);
        int rank = 0;
#pragma unroll
        for (int j = 0; j < 32; j++) {
            float vj = __shfl_sync(0xffffffffu, val, j);
            rank += (vj < val) || (vj == val && j < lane);
        }
        unsigned msk = __ballot_sync(0xffffffffu, rank == KNB - 1);
        float T = __shfl_sync(0xffffffffu, val, __ffs(msk) - 1);
        if (lane == 0) Tsh[w] = T;
    }
    __syncthreads();

    // ---- pass 2: compact passers from registers ----
#pragma unroll 1
    for (int q = 0; q < 16; q++) {
        float T = Tsh[q];
        float qx = qc[q * 3], qy = qc[q * 3 + 1], qz = qc[q * 3 + 2];
#pragma unroll
        for (int t = 0; t < 8; t++) {
            float d = fmaf(-2.f, fmaf(qx, P[t].x, fmaf(qy, P[t].y, qz * P[t].z)),
                           P[t].w);
            if (d <= T) {
                unsigned pos = atomicAdd(&cnt[q], 1u);
                if (pos < BCAP) {
                    int j = w * 256 + t * 32 + lane;
                    buf[q * BCAP + pos] =
                        ((unsigned long long)fkey(d) << 32) | (unsigned)j;
                }
            }
        }
    }
    __syncthreads();

    // ---- phase 3: warp w -> exact top-20 of query w via rank write ----
    {
        const unsigned nb = cnt[w];
        int* obase = g_idx + (b * NPTS + q0 + w) * KNB;
        if (nb <= BCAP) {
            const unsigned long long* myb = buf + w * BCAP;
#pragma unroll
            for (int u = 0; u < BCAP / 32; u++) {
                int t = lane + u * 32;
                if (t < (int)nb) {
                    unsigned long long mine = myb[t];
                    int rank = 0;
                    for (int i = 0; i < (int)nb; i++)
                        rank += (myb[i] < mine);       // broadcast LDS
                    if (rank < KNB)
                        obase[rank] = (int)(unsigned)(mine & 0xffffffffull);
                }
            }
        } else {
            // pathological fallback: exact repeated warp-min over all points
            float qx = qc[w * 3], qy = qc[w * 3 + 1], qz = qc[w * 3 + 2];
            unsigned long long last = 0;
            for (int r = 0; r < KNB; r++) {
                unsigned long long best = 0xffffffffffffffffull;
                for (int t = 0; t < NPTS / 32; t++) {
                    int j = t * 32 + lane;
                    float px = xb[j], py = xb[NPTS + j], pz = xb[2 * NPTS + j];
                    float pp = fmaf(px, px, fmaf(py, py, pz * pz));
                    float d = fmaf(-2.f, fmaf(qx, px, fmaf(qy, py, qz * pz)), pp);
                    unsigned long long kk =
                        ((unsigned long long)fkey(d) << 32) | (unsigned)j;
                    if (kk > last && kk < best) best = kk;
                }
#pragma unroll
                for (int d = 16; d; d >>= 1) {
                    unsigned long long o = __shfl_xor_sync(0xffffffffu, best, d);
                    best = (o < best) ? o : best;
                }
                if (lane == 0) obase[r] = (int)(unsigned)(best & 0xffffffffull);
                last = best;
            }
        }
    }
}

// ---------------------------------------------------------------------------
// Main: f16 mma.sync m16n8k16 GEMM with shfl-free A-operand build
// (byte-identical to round 15, 84.5us).
// ---------------------------------------------------------------------------
__global__ void __launch_bounds__(640, 1) main_mma(
    const float* __restrict__ x,     const float* __restrict__ b0,
    const float* __restrict__ b1,    const float* __restrict__ w_out,
    const float* __restrict__ g_out, const float* __restrict__ b_out,
    float* __restrict__ out)
{
    extern __shared__ float sm[];
    unsigned* wps = reinterpret_cast<unsigned*>(sm + OF_WPS);  // stride 132 u32
    float* zs  = sm + OF_Z;
    float* fts = sm + OF_FT;
    float* x1s = sm + OF_X1;
    float* w0f = sm + OF_W0;
    float* b0s = sm + OF_B0;
    float* b1s = sm + OF_B1;
    float* wos = sm + OF_WO;

    const int tid = threadIdx.x, lane = tid & 31, wid = tid >> 5;
    const int b = blockIdx.y, p0 = blockIdx.x * 16;
    const float* xb = x + b * 3 * NPTS;

    if (tid < 320) {
        int n = p0 + tid / 20;
        int jn = g_idx[(b * NPTS + n) * KNB + tid % 20];
        float xi0 = xb[n],  xi1 = xb[NPTS + n],  xi2 = xb[2 * NPTS + n];
        float xj0 = xb[jn], xj1 = xb[NPTS + jn], xj2 = xb[2 * NPTS + jn];
        float* fr = fts + tid * 9;
        fr[0] = xj0 - xi0; fr[1] = xj1 - xi1; fr[2] = xj2 - xi2;
        fr[3] = xi0; fr[4] = xi1; fr[5] = xi2;
    }
    for (int g4 = tid; g4 < 3072; g4 += 640) {
        uint4 v = reinterpret_cast<const uint4*>(g_wb)[g4];
        int row = g4 >> 5, pos4 = g4 & 31;
        *reinterpret_cast<uint4*>(wps + row * 132 + pos4 * 4) = v;
    }
    if (tid < 384) w0f[tid] = g_w0f[tid];
    if (tid < 64) { b0s[tid] = b0[tid]; b1s[tid] = b1[tid]; }
    if (tid < 192) wos[tid] = w_out[tid];
    __syncthreads();

    const int s = lane & 3, q = lane >> 2;
    const int rA = wid * 16 + q;

    float yr0[16], yr1[16];
    {
        const float* fA = fts + rA * 9;
        const float* fB = fts + (rA + 8) * 9;
        float a0 = fA[0], a1 = fA[1], a2 = fA[2], a3 = fA[3], a4 = fA[4], a5 = fA[5];
        float c0 = fB[0], c1 = fB[1], c2 = fB[2], c3 = fB[3], c4 = fB[4], c5 = fB[5];
#pragma unroll
        for (int k = 0; k < 16; k++) {
            int m = 4 * k + s;
            const float* wr = w0f + m * 6;
            float bb = b0s[m];
            float u = bb, v = bb;
            u = fmaf(wr[0], a0, u); v = fmaf(wr[0], c0, v);
            u = fmaf(wr[1], a1, u); v = fmaf(wr[1], c1, v);
            u = fmaf(wr[2], a2, u); v = fmaf(wr[2], c2, v);
            u = fmaf(wr[3], a3, u); v = fmaf(wr[3], c3, v);
            u = fmaf(wr[4], a4, u); v = fmaf(wr[4], c4, v);
            u = fmaf(wr[5], a5, u); v = fmaf(wr[5], c5, v);
            yr0[k] = lrelu(u);
            yr1[k] = lrelu(v);
        }
    }

    float ftA[6], ftB[6];
#pragma unroll
    for (int i = 0; i < 6; i++) {
        ftA[i] = fts[rA * 9 + i];
        ftB[i] = fts[(rA + 8) * 9 + i];
    }

    float dA[8][4];
#pragma unroll
    for (int nt = 0; nt < 8; nt++)
#pragma unroll
        for (int u = 0; u < 4; u++) dA[nt][u] = 0.f;

    const unsigned* wbase = wps + s * 132 + q * 16;

#pragma unroll
    for (int k16 = 0; k16 < 24; k16++) {
        const int c  = k16 >> 2;
        const int kb = 4 * (k16 & 3);
        const float fA = ftA[c], fB = ftB[c];

        uint32_t a0 = packh2(yr0[kb] * fA,     yr0[kb + 1] * fA);
        uint32_t a1 = packh2(yr1[kb] * fB,     yr1[kb + 1] * fB);
        uint32_t a2 = packh2(yr0[kb + 2] * fA, yr0[kb + 3] * fA);
        uint32_t a3 = packh2(yr1[kb + 2] * fB, yr1[kb + 3] * fB);

        const unsigned* wrow = wbase + k16 * 4 * 132;
        uint4 B0a = *reinterpret_cast<const uint4*>(wrow);
        uint4 B0b = *reinterpret_cast<const uint4*>(wrow + 4);
        uint4 B1a = *reinterpret_cast<const uint4*>(wrow + 8);
        uint4 B1b = *reinterpret_cast<const uint4*>(wrow + 12);

        MMA_F16(dA[0], a0, a1, a2, a3, B0a.x, B1a.x);
        MMA_F16(dA[1], a0, a1, a2, a3, B0a.y, B1a.y);
        MMA_F16(dA[2], a0, a1, a2, a3, B0a.z, B1a.z);
        MMA_F16(dA[3], a0, a1, a2, a3, B0a.w, B1a.w);
        MMA_F16(dA[4], a0, a1, a2, a3, B0b.x, B1b.x);
        MMA_F16(dA[5], a0, a1, a2, a3, B0b.y, B1b.y);
        MMA_F16(dA[6], a0, a1, a2, a3, B0b.z, B1b.z);
        MMA_F16(dA[7], a0, a1, a2, a3, B0b.w, B1b.w);
    }

    __syncwarp();
#pragma unroll
    for (int nt = 0; nt < 8; nt++) {
        int c = nt * 8 + s * 2;
        float bc0 = b1s[c], bc1 = b1s[c + 1];
        *reinterpret_cast<float2*>(zs + rA * 66 + c) =
            make_float2(lrelu(dA[nt][0] + bc0), lrelu(dA[nt][1] + bc1));
        *reinterpret_cast<float2*>(zs + (rA + 8) * 66 + c) =
            make_float2(lrelu(dA[nt][2] + bc0), lrelu(dA[nt][3] + bc1));
    }
    __syncthreads();

    for (int it = tid; it < 16 * 64; it += 640) {
        int p = it >> 6, col = it & 63;
        const float* zr = zs + (p * 20) * 66 + col;
        float m = -3.4e38f;
#pragma unroll
        for (int kk = 0; kk < 20; kk++) m = fmaxf(m, zr[kk * 66]);
        x1s[it] = m;
    }
    __syncthreads();

    if (tid < 48) {
        int oo = tid >> 4, pt = tid & 15;
        const float* wr = wos + oo * 64;
        const float* xr = x1s + pt * 64;
        float sum = 0.f;
#pragma unroll
        for (int o = 0; o < 64; o++) sum = fmaf(wr[o], xr[o], sum);
        float v = sum * (g_out[oo] * rsqrtf(1.f + EPSV)) + b_out[oo];
        out[(b * 3 + oo) * NPTS + p0 + pt] = lrelu(v);
    }
}

// ---------------------------------------------------------------------------
extern "C" void kernel_launch(void* const* d_in, const int* in_sizes, int n_in,
                              void* d_out, int out_size) {
    const float* x     = (const float*)d_in[0];
    const float* w0    = (const float*)d_in[1];
    const float* g0    = (const float*)d_in[2];
    const float* b0    = (const float*)d_in[3];
    const float* w1    = (const float*)d_in[4];
    const float* g1    = (const float*)d_in[5];
    const float* b1    = (const float*)d_in[6];
    const float* w_out = (const float*)d_in[7];
    const float* g_out = (const float*)d_in[8];
    const float* b_out = (const float*)d_in[9];
    float* out = (float*)d_out;

    const int main_smem = SM_FLOATS * 4;                     // 153600

    cudaFuncSetAttribute(knn_prep_kernel, cudaFuncAttributeMaxDynamicSharedMemorySize,
                         KS_TOT);
    cudaFuncSetAttribute(main_mma, cudaFuncAttributeMaxDynamicSharedMemorySize,
                         main_smem);

    knn_prep_kernel<<<dim3(NPTS / 16, BATCH), 512, KS_TOT>>>(x, w0, g0, w1, g1);
    main_mma<<<dim3(NPTS / 16, BATCH), 640, main_smem>>>(x, b0, b1, w_out,
                                                         g_out, b_out, out);
}